// round 10
// baseline (speedup 1.0000x reference)
#include <cuda_runtime.h>
#include <cuda_bf16.h>
#include <cstdint>

#define TOK 49
#define HDIM 32
#define NH 8
#define NWIN 4096
#define MTOT (NWIN * TOK)   /* 200704 */
#define KDIM 256
#define NMASK 64
#define BMROW 50
#define BMSTRIDE 2452

// ---------------- scratch (device globals: allocation-free) ----------------
__device__ float g_q[NWIN * NH * TOK * HDIM];   // [b,h,t,d]
__device__ float g_k[NWIN * NH * TOK * HDIM];
__device__ float g_v[NWIN * NH * TOK * HDIM];
__device__ float g_att[MTOT * KDIM];            // [b*49+t, h*32+d] (tf32-rounded)
__device__ float g_bm[NMASK * NH * BMSTRIDE];   // fused bias+mask per (w,h)
__device__ float g_wq[768 * KDIM];              // qkv_w, tf32-rounded
__device__ float g_wp[KDIM * KDIM];             // proj_w, tf32-rounded

__device__ __forceinline__ float4 ld4(const float* p) {
    return *reinterpret_cast<const float4*>(p);
}
__device__ __forceinline__ void st4(float* p, float4 v) {
    *reinterpret_cast<float4*>(p) = v;
}
__device__ __forceinline__ void st2(float* p, float2 v) {
    *reinterpret_cast<float2*>(p) = v;
}
__device__ __forceinline__ uint32_t f2tf(float f) {
    uint32_t u;
    asm("cvt.rna.tf32.f32 %0, %1;" : "=r"(u) : "f"(f));
    return u;
}
__device__ __forceinline__ float tfr(float f) { return __uint_as_float(f2tf(f)); }
__device__ __forceinline__ void cp16(float* smem_dst, const float* gmem_src) {
    uint32_t s = (uint32_t)__cvta_generic_to_shared(smem_dst);
    asm volatile("cp.async.cg.shared.global [%0], [%1], 16;" :: "r"(s), "l"(gmem_src));
}
__device__ __forceinline__ void mma_tf32(float c[4],
                                         uint32_t a0, uint32_t a1, uint32_t a2, uint32_t a3,
                                         uint32_t b0, uint32_t b1) {
    asm volatile(
        "mma.sync.aligned.m16n8k8.row.col.f32.tf32.tf32.f32 "
        "{%0,%1,%2,%3}, {%4,%5,%6,%7}, {%8,%9}, {%0,%1,%2,%3};"
        : "+f"(c[0]), "+f"(c[1]), "+f"(c[2]), "+f"(c[3])
        : "r"(a0), "r"(a1), "r"(a2), "r"(a3), "r"(b0), "r"(b1));
}

// ---------------------------------------------------------------------------
// elementwise tf32 (rna) pre-round (weights only)
// ---------------------------------------------------------------------------
__global__ void round4(const float* __restrict__ in, float* __restrict__ out) {
    const size_t i = (size_t)(blockIdx.x * blockDim.x + threadIdx.x) * 4;
    float4 v = ld4(in + i);
    v.x = tfr(v.x); v.y = tfr(v.y); v.z = tfr(v.z); v.w = tfr(v.w);
    st4(out + i, v);
}

// ---------------------------------------------------------------------------
// tf32 tensor-core GEMM (NT), 4-stage cp.async pipeline, dynamic smem.
// Block 128(m) x 64(n), BK=16, 8 warps (4m x 2n), warp tile 32x32.
// 3 CTAs/SM (24 warps) for latency hiding. One __syncthreads per K-tile.
// MODE 0: A = x raw fp32, fragments cvt'd in-loop; scatter epilogue (q scaled).
// MODE 1: A already tf32-rounded; plain epilogue.
// ---------------------------------------------------------------------------
#define RS 20                   // smem row stride (floats)
#define STG 4                   // pipeline stages
#define AF (128 * RS)           // A floats per stage
#define BF (64 * RS)            // B floats per stage
#define STGF (AF + BF)          // floats per stage

extern __shared__ float smx[];

template <int MODE>
__global__ __launch_bounds__(256, 3)
void gemm_tf32(const float* __restrict__ A, const float* __restrict__ B,
               const float* __restrict__ bias, float* __restrict__ C, int N)
{
    const int tid  = threadIdx.x;
    const int m0   = blockIdx.y * 128;
    const int n0   = blockIdx.x * 64;
    const int warp = tid >> 5;
    const int lane = tid & 31;
    const int g    = lane >> 2;
    const int tig  = lane & 3;
    const int wm   = warp & 3;        // 4 m-subtiles of 32 rows
    const int wn   = warp >> 2;       // 2 n-subtiles of 32 cols

    // A loader: row = tid>>1 (0..127), float col = (tid&1)*8, two cp16
    const int lra = tid >> 1;
    const int lca = (tid & 1) * 8;
    const float* Ag = A + (size_t)(m0 + lra) * KDIM + lca;
    const int adst = lra * RS + lca;
    // B loader: row = tid>>2 (0..63), float col = (tid&3)*4, one cp16
    const int lrb = tid >> 2;
    const int lcb = (tid & 3) * 4;
    const float* Bg = B + (size_t)(n0 + lrb) * KDIM + lcb;
    const int bdst = lrb * RS + lcb;

    float acc[2][4][4];
#pragma unroll
    for (int mi = 0; mi < 2; mi++)
#pragma unroll
        for (int ni = 0; ni < 4; ni++)
#pragma unroll
            for (int e = 0; e < 4; e++) acc[mi][ni][e] = 0.f;

    auto issue = [&](int s, int kt) {
        float* As = smx + s * STGF;
        float* Bs = As + AF;
        cp16(&As[adst],     Ag + kt);
        cp16(&As[adst + 4], Ag + kt + 4);
        cp16(&Bs[bdst],     Bg + kt);
        asm volatile("cp.async.commit_group;");
    };

    const int NT = KDIM / 16;
#pragma unroll
    for (int s = 0; s < STG - 1; s++) issue(s, s * 16);

#pragma unroll 1
    for (int iter = 0; iter < NT; iter++) {
        asm volatile("cp.async.wait_group %0;" :: "n"(STG - 2));
        __syncthreads();
        if (iter + STG - 1 < NT) issue((iter + STG - 1) % STG, (iter + STG - 1) * 16);
        else asm volatile("cp.async.commit_group;");

        const int st = iter % STG;
        const uint32_t* sA = reinterpret_cast<const uint32_t*>(smx + st * STGF);
        const uint32_t* sB = sA + AF;
#pragma unroll
        for (int k8 = 0; k8 < 16; k8 += 8) {
            uint32_t a[2][4], bf[4][2];
#pragma unroll
            for (int mi = 0; mi < 2; mi++) {
                const int mg = (wm * 32 + mi * 16 + g) * RS;
                a[mi][0] = sA[mg + k8 + tig];
                a[mi][1] = sA[mg + 8 * RS + k8 + tig];
                a[mi][2] = sA[mg + k8 + tig + 4];
                a[mi][3] = sA[mg + 8 * RS + k8 + tig + 4];
                if (MODE == 0) {
#pragma unroll
                    for (int e = 0; e < 4; e++)
                        a[mi][e] = f2tf(__uint_as_float(a[mi][e]));
                }
            }
#pragma unroll
            for (int ni = 0; ni < 4; ni++) {
                const int ng = (wn * 32 + ni * 8 + g) * RS;
                bf[ni][0] = sB[ng + k8 + tig];
                bf[ni][1] = sB[ng + k8 + tig + 4];
            }
#pragma unroll
            for (int mi = 0; mi < 2; mi++)
#pragma unroll
                for (int ni = 0; ni < 4; ni++)
                    mma_tf32(acc[mi][ni], a[mi][0], a[mi][1], a[mi][2], a[mi][3],
                             bf[ni][0], bf[ni][1]);
        }
    }

    if (MODE == 0) {
        const float SC = 0.17677669529663687f;
#pragma unroll
        for (int mi = 0; mi < 2; mi++) {
#pragma unroll
            for (int half = 0; half < 2; half++) {
                const int m  = m0 + wm * 32 + mi * 16 + g + half * 8;
                const int bw = m / TOK;
                const int t  = m - bw * TOK;
#pragma unroll
                for (int ni = 0; ni < 4; ni++) {
                    const int n     = n0 + wn * 32 + ni * 8 + 2 * tig;
                    const int which = n >> 8;
                    const int h     = (n >> 5) & 7;
                    const int d     = n & 31;
                    float2 v;
                    v.x = acc[mi][ni][half * 2 + 0] + bias[n + 0];
                    v.y = acc[mi][ni][half * 2 + 1] + bias[n + 1];
                    if (which == 0) { v.x *= SC; v.y *= SC; }
                    float* dst = (which == 0) ? g_q : (which == 1) ? g_k : g_v;
                    st2(&dst[(size_t)((bw * NH + h) * TOK + t) * HDIM + d], v);
                }
            }
        }
    } else {
#pragma unroll
        for (int mi = 0; mi < 2; mi++) {
#pragma unroll
            for (int half = 0; half < 2; half++) {
                const int m = m0 + wm * 32 + mi * 16 + g + half * 8;
#pragma unroll
                for (int ni = 0; ni < 4; ni++) {
                    const int n = n0 + wn * 32 + ni * 8 + 2 * tig;
                    float2 v;
                    v.x = acc[mi][ni][half * 2 + 0] + bias[n + 0];
                    v.y = acc[mi][ni][half * 2 + 1] + bias[n + 1];
                    st2(C + (size_t)m * N + n, v);
                }
            }
        }
    }
}

// ---------------------------------------------------------------------------
// Precompute fused bias+mask (row stride 50)
// ---------------------------------------------------------------------------
__global__ void bm_precompute(const float* __restrict__ bias_table,
                              const int* __restrict__ rel_index,
                              const float* __restrict__ mask)
{
    const int w = blockIdx.x >> 3;
    float* dst = g_bm + (size_t)blockIdx.x * BMSTRIDE;
    const int h = blockIdx.x & 7;
    const float* mrow = mask + (size_t)w * (TOK * TOK);
    for (int e = threadIdx.x; e < TOK * TOK; e += 256) {
        const int i = e / TOK;
        const int j = e - i * TOK;
        dst[i * BMROW + j] = bias_table[rel_index[e] * NH + h] + mrow[e];
    }
}

// ---------------------------------------------------------------------------
// Tensor-core attention (unchanged — known good)
// ---------------------------------------------------------------------------
#define STQ 36
#define STV 60

__global__ __launch_bounds__(128)
void attn_mma()
{
    __shared__ float sm[6240];
    float* Qs = sm;
    float* Ks = sm + 2304;
    float* Vt = sm + 4320;
    float* Ps = sm;

    const int tid  = threadIdx.x;
    const int warp = tid >> 5;
    const int lane = tid & 31;
    const int g    = lane >> 2;
    const int tig  = lane & 3;
    const int bh   = blockIdx.x;
    const int b    = bh >> 3;
    const int h    = bh & 7;
    const int base = bh * (TOK * HDIM);

    for (int idx = tid; idx < 64 * 8; idx += 128) {
        const int r = idx >> 3;
        const int c = (idx & 7) * 4;
        float4 v = (r < TOK) ? ld4(g_q + base + r * HDIM + c)
                             : make_float4(0.f, 0.f, 0.f, 0.f);
        Qs[r * STQ + c + 0] = tfr(v.x);
        Qs[r * STQ + c + 1] = tfr(v.y);
        Qs[r * STQ + c + 2] = tfr(v.z);
        Qs[r * STQ + c + 3] = tfr(v.w);
    }
    for (int idx = tid; idx < 56 * 8; idx += 128) {
        const int r = idx >> 3;
        const int c = (idx & 7) * 4;
        float4 kv, vv;
        if (r < TOK) {
            kv = ld4(g_k + base + r * HDIM + c);
            vv = ld4(g_v + base + r * HDIM + c);
        } else {
            kv = make_float4(0.f, 0.f, 0.f, 0.f);
            vv = kv;
        }
        Ks[r * STQ + c + 0] = tfr(kv.x);
        Ks[r * STQ + c + 1] = tfr(kv.y);
        Ks[r * STQ + c + 2] = tfr(kv.z);
        Ks[r * STQ + c + 3] = tfr(kv.w);
        Vt[(c + 0) * STV + r] = tfr(vv.x);
        Vt[(c + 1) * STV + r] = tfr(vv.y);
        Vt[(c + 2) * STV + r] = tfr(vv.z);
        Vt[(c + 3) * STV + r] = tfr(vv.w);
    }
    __syncthreads();

    const int mrow = warp * 16;
    const uint32_t* Qu = reinterpret_cast<const uint32_t*>(Qs);
    const uint32_t* Ku = reinterpret_cast<const uint32_t*>(Ks);
    const uint32_t* Vu = reinterpret_cast<const uint32_t*>(Vt);

    float sacc[7][4];
#pragma unroll
    for (int j = 0; j < 7; j++)
#pragma unroll
        for (int e = 0; e < 4; e++) sacc[j][e] = 0.f;

#pragma unroll
    for (int kt = 0; kt < 4; kt++) {
        const int ko = kt * 8;
        uint32_t a0 = Qu[(mrow + g) * STQ + ko + tig];
        uint32_t a1 = Qu[(mrow + g + 8) * STQ + ko + tig];
        uint32_t a2 = Qu[(mrow + g) * STQ + ko + tig + 4];
        uint32_t a3 = Qu[(mrow + g + 8) * STQ + ko + tig + 4];
#pragma unroll
        for (int j = 0; j < 7; j++) {
            uint32_t b0 = Ku[(j * 8 + g) * STQ + ko + tig];
            uint32_t b1 = Ku[(j * 8 + g) * STQ + ko + tig + 4];
            mma_tf32(sacc[j], a0, a1, a2, a3, b0, b1);
        }
    }

    const int r1 = mrow + g;
    const int r2 = r1 + 8;
    const float* bmb = g_bm + (size_t)(((b & (NMASK - 1)) << 3) + h) * BMSTRIDE;
    const float* bm1 = bmb + (r1 < TOK ? r1 : 48) * BMROW;
    const float* bm2 = bmb + (r2 < TOK ? r2 : 48) * BMROW;

    float mx1 = -1e30f, mx2 = -1e30f;
#pragma unroll
    for (int j = 0; j < 7; j++) {
        const int cc = j * 8 + 2 * tig;
        const float2 bb1 = *reinterpret_cast<const float2*>(bm1 + cc);
        const float2 bb2 = *reinterpret_cast<const float2*>(bm2 + cc);
        sacc[j][0] = (cc     < TOK) ? sacc[j][0] + bb1.x : -1e30f;
        sacc[j][1] = (cc + 1 < TOK) ? sacc[j][1] + bb1.y : -1e30f;
        sacc[j][2] = (cc     < TOK) ? sacc[j][2] + bb2.x : -1e30f;
        sacc[j][3] = (cc + 1 < TOK) ? sacc[j][3] + bb2.y : -1e30f;
        mx1 = fmaxf(mx1, fmaxf(sacc[j][0], sacc[j][1]));
        mx2 = fmaxf(mx2, fmaxf(sacc[j][2], sacc[j][3]));
    }
    mx1 = fmaxf(mx1, __shfl_xor_sync(0xffffffffu, mx1, 1));
    mx1 = fmaxf(mx1, __shfl_xor_sync(0xffffffffu, mx1, 2));
    mx2 = fmaxf(mx2, __shfl_xor_sync(0xffffffffu, mx2, 1));
    mx2 = fmaxf(mx2, __shfl_xor_sync(0xffffffffu, mx2, 2));

    float s1 = 0.f, s2 = 0.f;
#pragma unroll
    for (int j = 0; j < 7; j++) {
        sacc[j][0] = __expf(sacc[j][0] - mx1);
        sacc[j][1] = __expf(sacc[j][1] - mx1);
        sacc[j][2] = __expf(sacc[j][2] - mx2);
        sacc[j][3] = __expf(sacc[j][3] - mx2);
        s1 += sacc[j][0] + sacc[j][1];
        s2 += sacc[j][2] + sacc[j][3];
    }
    s1 += __shfl_xor_sync(0xffffffffu, s1, 1);
    s1 += __shfl_xor_sync(0xffffffffu, s1, 2);
    s2 += __shfl_xor_sync(0xffffffffu, s2, 1);
    s2 += __shfl_xor_sync(0xffffffffu, s2, 2);
    const float inv1 = 1.f / s1;
    const float inv2 = 1.f / s2;

    __syncthreads();
#pragma unroll
    for (int j = 0; j < 7; j++) {
        const int cc = j * 8 + 2 * tig;
        st2(&Ps[r1 * STV + cc], make_float2(tfr(sacc[j][0] * inv1), tfr(sacc[j][1] * inv1)));
        st2(&Ps[r2 * STV + cc], make_float2(tfr(sacc[j][2] * inv2), tfr(sacc[j][3] * inv2)));
    }
    __syncwarp();

    const uint32_t* Pu = reinterpret_cast<const uint32_t*>(Ps);
    float oacc[4][4];
#pragma unroll
    for (int nt = 0; nt < 4; nt++)
#pragma unroll
        for (int e = 0; e < 4; e++) oacc[nt][e] = 0.f;

#pragma unroll
    for (int kt = 0; kt < 7; kt++) {
        const int ko = kt * 8;
        uint32_t a0 = Pu[(mrow + g) * STV + ko + tig];
        uint32_t a1 = Pu[(mrow + g + 8) * STV + ko + tig];
        uint32_t a2 = Pu[(mrow + g) * STV + ko + tig + 4];
        uint32_t a3 = Pu[(mrow + g + 8) * STV + ko + tig + 4];
#pragma unroll
        for (int nt = 0; nt < 4; nt++) {
            uint32_t b0 = Vu[(nt * 8 + g) * STV + ko + tig];
            uint32_t b1 = Vu[(nt * 8 + g) * STV + ko + tig + 4];
            mma_tf32(oacc[nt], a0, a1, a2, a3, b0, b1);
        }
    }

#pragma unroll
    for (int nt = 0; nt < 4; nt++) {
        const int d = nt * 8 + 2 * tig;
        if (r1 < TOK)
            st2(&g_att[(size_t)(b * TOK + r1) * KDIM + h * HDIM + d],
                make_float2(tfr(oacc[nt][0]), tfr(oacc[nt][1])));
        if (r2 < TOK)
            st2(&g_att[(size_t)(b * TOK + r2) * KDIM + h * HDIM + d],
                make_float2(tfr(oacc[nt][2]), tfr(oacc[nt][3])));
    }
}

// ---------------------------------------------------------------------------
extern "C" void kernel_launch(void* const* d_in, const int* in_sizes, int n_in,
                              void* d_out, int out_size)
{
    const float* x          = (const float*)d_in[0];
    const float* mask       = (const float*)d_in[1];
    const float* qkv_w      = (const float*)d_in[2];
    const float* qkv_b      = (const float*)d_in[3];
    const float* proj_w     = (const float*)d_in[4];
    const float* proj_b     = (const float*)d_in[5];
    const float* bias_table = (const float*)d_in[6];
    const int*   rel_index  = (const int*)d_in[7];
    float*       out        = (float*)d_out;

    float *p_wq, *p_wp, *p_att;
    cudaGetSymbolAddress((void**)&p_wq,  g_wq);
    cudaGetSymbolAddress((void**)&p_wp,  g_wp);
    cudaGetSymbolAddress((void**)&p_att, g_att);

    const int smbytes = STG * STGF * 4;   // 61440 B
    cudaFuncSetAttribute(gemm_tf32<0>, cudaFuncAttributeMaxDynamicSharedMemorySize, smbytes);
    cudaFuncSetAttribute(gemm_tf32<1>, cudaFuncAttributeMaxDynamicSharedMemorySize, smbytes);

    round4<<<(768 * KDIM) / 4 / 256, 256>>>(qkv_w, p_wq);
    round4<<<(KDIM * KDIM) / 4 / 256, 256>>>(proj_w, p_wp);

    bm_precompute<<<NMASK * NH, 256>>>(bias_table, rel_index, mask);

    dim3 g1(768 / 64, MTOT / 128);
    gemm_tf32<0><<<g1, 256, smbytes>>>(x, p_wq, qkv_b, nullptr, 768);

    attn_mma<<<NWIN * NH, 128>>>();

    dim3 g2(KDIM / 64, MTOT / 128);
    gemm_tf32<1><<<g2, 256, smbytes>>>(p_att, p_wp, proj_b, out, KDIM);
}

// round 12
// speedup vs baseline: 1.5956x; 1.5956x over previous
#include <cuda_runtime.h>
#include <cuda_fp16.h>
#include <cstdint>

#define TOK 49
#define HDIM 32
#define NH 8
#define NWIN 4096
#define MTOT (NWIN * TOK)   /* 200704 */
#define KDIM 256
#define NMASK 64
#define BMROW 50
#define BMSTRIDE 2452

// ---------------- scratch (device globals: allocation-free) ----------------
__device__ float  g_q[NWIN * NH * TOK * HDIM];   // [b,h,t,d]
__device__ float  g_k[NWIN * NH * TOK * HDIM];
__device__ float  g_v[NWIN * NH * TOK * HDIM];
__device__ __half g_ath[MTOT * KDIM];            // attention out, fp16
__device__ float  g_bm[NMASK * NH * BMSTRIDE];   // fused bias+mask per (w,h)
__device__ __half g_xh[MTOT * KDIM];             // x, fp16
__device__ __half g_wqh[768 * KDIM];             // qkv_w, fp16
__device__ __half g_wph[KDIM * KDIM];            // proj_w, fp16

__device__ __forceinline__ float4 ld4(const float* p) {
    return *reinterpret_cast<const float4*>(p);
}
__device__ __forceinline__ void st4(float* p, float4 v) {
    *reinterpret_cast<float4*>(p) = v;
}
__device__ __forceinline__ void st2(float* p, float2 v) {
    *reinterpret_cast<float2*>(p) = v;
}
__device__ __forceinline__ uint32_t f2tf(float f) {
    uint32_t u;
    asm("cvt.rna.tf32.f32 %0, %1;" : "=r"(u) : "f"(f));
    return u;
}
__device__ __forceinline__ float tfr(float f) { return __uint_as_float(f2tf(f)); }
__device__ __forceinline__ void cp16at(uint32_t smem_addr, const void* gmem_src) {
    asm volatile("cp.async.cg.shared.global [%0], [%1], 16;" :: "r"(smem_addr), "l"(gmem_src));
}

// fp16 tensor-core mma, fp32 accumulate
__device__ __forceinline__ void mma_f16(float c[4],
                                        uint32_t a0, uint32_t a1, uint32_t a2, uint32_t a3,
                                        uint32_t b0, uint32_t b1) {
    asm volatile(
        "mma.sync.aligned.m16n8k16.row.col.f32.f16.f16.f32 "
        "{%0,%1,%2,%3}, {%4,%5,%6,%7}, {%8,%9}, {%0,%1,%2,%3};"
        : "+f"(c[0]), "+f"(c[1]), "+f"(c[2]), "+f"(c[3])
        : "r"(a0), "r"(a1), "r"(a2), "r"(a3), "r"(b0), "r"(b1));
}
// tf32 mma (attention)
__device__ __forceinline__ void mma_tf32(float c[4],
                                         uint32_t a0, uint32_t a1, uint32_t a2, uint32_t a3,
                                         uint32_t b0, uint32_t b1) {
    asm volatile(
        "mma.sync.aligned.m16n8k8.row.col.f32.tf32.tf32.f32 "
        "{%0,%1,%2,%3}, {%4,%5,%6,%7}, {%8,%9}, {%0,%1,%2,%3};"
        : "+f"(c[0]), "+f"(c[1]), "+f"(c[2]), "+f"(c[3])
        : "r"(a0), "r"(a1), "r"(a2), "r"(a3), "r"(b0), "r"(b1));
}

// ---------------------------------------------------------------------------
// fp32 -> fp16 conversion (8 elems/thread, 16B stores)
// ---------------------------------------------------------------------------
__global__ void cvt2h(const float* __restrict__ in, __half* __restrict__ out) {
    const size_t i = (size_t)(blockIdx.x * blockDim.x + threadIdx.x) * 8;
    float4 v0 = ld4(in + i), v1 = ld4(in + i + 4);
    __half2 h[4];
    h[0] = __floats2half2_rn(v0.x, v0.y);
    h[1] = __floats2half2_rn(v0.z, v0.w);
    h[2] = __floats2half2_rn(v1.x, v1.y);
    h[3] = __floats2half2_rn(v1.z, v1.w);
    *reinterpret_cast<uint4*>(out + i) = *reinterpret_cast<uint4*>(h);
}

// ---------------------------------------------------------------------------
// fp16 tensor-core GEMM (NT): C[m,n] = sum_k A[m,k]*B[n,k] + bias[n]
// Block 128x128, BK=32 halves (16 words/row, RS=20 words), 8 warps (2m x 4n),
// warp tile 64x32, m16n8k16, 4-stage cp.async pipeline, NT=8 K-tiles.
// Index arithmetic identical to the proven tf32 kernel (conflict-free).
// MODE 0: scatter to g_q/g_k/g_v (q scaled). MODE 1: plain epilogue.
// ---------------------------------------------------------------------------
#define RS 20                  // smem row stride in 4B words (= 40 halves)
#define STG 4
#define AFW (128 * RS)         // words per A stage
#define STGW (2 * AFW)         // words per stage (A then B)

extern __shared__ uint32_t smw[];

template <int MODE>
__global__ __launch_bounds__(256, 2)
void gemm_h(const __half* __restrict__ A, const __half* __restrict__ B,
            const float* __restrict__ bias, float* __restrict__ C, int N)
{
    const int tid  = threadIdx.x;
    const int m0   = blockIdx.y * 128;
    const int n0   = blockIdx.x * 128;
    const int warp = tid >> 5;
    const int lane = tid & 31;
    const int g    = lane >> 2;
    const int tig  = lane & 3;
    const int wm   = warp & 1;
    const int wn   = warp >> 1;

    // loader: row = tid>>1 (0..127), halves offset (tid&1)*16, two cp16 each
    const int lr  = tid >> 1;
    const int lch = (tid & 1) * 16;      // half offset within 32-half row
    const __half* Ag = A + (size_t)(m0 + lr) * KDIM + lch;
    const __half* Bg = B + (size_t)(n0 + lr) * KDIM + lch;
    uint32_t sbase;
    asm("{ .reg .u64 t; cvta.to.shared.u64 t, %1; cvt.u32.u64 %0, t; }"
        : "=r"(sbase) : "l"(smw));
    const uint32_t adst = sbase + (uint32_t)(lr * RS + (lch >> 1)) * 4;

    float acc[4][4][4];
#pragma unroll
    for (int mi = 0; mi < 4; mi++)
#pragma unroll
        for (int ni = 0; ni < 4; ni++)
#pragma unroll
            for (int e = 0; e < 4; e++) acc[mi][ni][e] = 0.f;

    auto issue = [&](int s, int kt) {
        const uint32_t so = (uint32_t)(s * STGW) * 4;
        cp16at(adst + so,      Ag + kt);
        cp16at(adst + so + 16, Ag + kt + 8);
        cp16at(adst + so + AFW * 4,      Bg + kt);
        cp16at(adst + so + AFW * 4 + 16, Bg + kt + 8);
        asm volatile("cp.async.commit_group;");
    };

    const int NT = KDIM / 32;   // 8
#pragma unroll
    for (int s = 0; s < STG - 1; s++) issue(s, s * 32);

#pragma unroll 1
    for (int iter = 0; iter < NT; iter++) {
        asm volatile("cp.async.wait_group %0;" :: "n"(STG - 2));
        __syncthreads();
        if (iter + STG - 1 < NT) issue((iter + STG - 1) % STG, (iter + STG - 1) * 32);
        else asm volatile("cp.async.commit_group;");

        const uint32_t* sA = smw + (iter % STG) * STGW;
        const uint32_t* sB = sA + AFW;
#pragma unroll
        for (int k8 = 0; k8 < 16; k8 += 8) {     // two m16n8k16 steps
            uint32_t a[4][4], bf[4][2];
#pragma unroll
            for (int mi = 0; mi < 4; mi++) {
                const int mg = (wm * 64 + mi * 16 + g) * RS;
                a[mi][0] = sA[mg + k8 + tig];
                a[mi][1] = sA[mg + 8 * RS + k8 + tig];
                a[mi][2] = sA[mg + k8 + tig + 4];
                a[mi][3] = sA[mg + 8 * RS + k8 + tig + 4];
            }
#pragma unroll
            for (int ni = 0; ni < 4; ni++) {
                const int ng = (wn * 32 + ni * 8 + g) * RS;
                bf[ni][0] = sB[ng + k8 + tig];
                bf[ni][1] = sB[ng + k8 + tig + 4];
            }
#pragma unroll
            for (int mi = 0; mi < 4; mi++)
#pragma unroll
                for (int ni = 0; ni < 4; ni++)
                    mma_f16(acc[mi][ni], a[mi][0], a[mi][1], a[mi][2], a[mi][3],
                            bf[ni][0], bf[ni][1]);
        }
    }

    // epilogue: c0/c1 -> (row g, cols 2*tig..+1), c2/c3 -> (row g+8)
    if (MODE == 0) {
        const float SC = 0.17677669529663687f;
#pragma unroll
        for (int mi = 0; mi < 4; mi++) {
#pragma unroll
            for (int half = 0; half < 2; half++) {
                const int m  = m0 + wm * 64 + mi * 16 + g + half * 8;
                const int bw = m / TOK;
                const int t  = m - bw * TOK;
#pragma unroll
                for (int ni = 0; ni < 4; ni++) {
                    const int n     = n0 + wn * 32 + ni * 8 + 2 * tig;
                    const int which = n >> 8;
                    const int h     = (n >> 5) & 7;
                    const int d     = n & 31;
                    float2 v;
                    v.x = acc[mi][ni][half * 2 + 0] + bias[n + 0];
                    v.y = acc[mi][ni][half * 2 + 1] + bias[n + 1];
                    if (which == 0) { v.x *= SC; v.y *= SC; }
                    float* dst = (which == 0) ? g_q : (which == 1) ? g_k : g_v;
                    st2(&dst[(size_t)((bw * NH + h) * TOK + t) * HDIM + d], v);
                }
            }
        }
    } else {
#pragma unroll
        for (int mi = 0; mi < 4; mi++) {
#pragma unroll
            for (int half = 0; half < 2; half++) {
                const int m = m0 + wm * 64 + mi * 16 + g + half * 8;
#pragma unroll
                for (int ni = 0; ni < 4; ni++) {
                    const int n = n0 + wn * 32 + ni * 8 + 2 * tig;
                    float2 v;
                    v.x = acc[mi][ni][half * 2 + 0] + bias[n + 0];
                    v.y = acc[mi][ni][half * 2 + 1] + bias[n + 1];
                    st2(C + (size_t)m * N + n, v);
                }
            }
        }
    }
}

// ---------------------------------------------------------------------------
// Precompute fused bias+mask (row stride 50)
// ---------------------------------------------------------------------------
__global__ void bm_precompute(const float* __restrict__ bias_table,
                              const int* __restrict__ rel_index,
                              const float* __restrict__ mask)
{
    const int w = blockIdx.x >> 3;
    float* dst = g_bm + (size_t)blockIdx.x * BMSTRIDE;
    const int h = blockIdx.x & 7;
    const float* mrow = mask + (size_t)w * (TOK * TOK);
    for (int e = threadIdx.x; e < TOK * TOK; e += 256) {
        const int i = e / TOK;
        const int j = e - i * TOK;
        dst[i * BMROW + j] = bias_table[rel_index[e] * NH + h] + mrow[e];
    }
}

// ---------------------------------------------------------------------------
// Tensor-core attention (tf32 mma, unchanged) — output now fp16 into g_ath
// ---------------------------------------------------------------------------
#define STQ 36
#define STV 60

__global__ __launch_bounds__(128)
void attn_mma()
{
    __shared__ float sm[6240];
    float* Qs = sm;
    float* Ks = sm + 2304;
    float* Vt = sm + 4320;
    float* Ps = sm;

    const int tid  = threadIdx.x;
    const int warp = tid >> 5;
    const int lane = tid & 31;
    const int g    = lane >> 2;
    const int tig  = lane & 3;
    const int bh   = blockIdx.x;
    const int b    = bh >> 3;
    const int h    = bh & 7;
    const int base = bh * (TOK * HDIM);

    for (int idx = tid; idx < 64 * 8; idx += 128) {
        const int r = idx >> 3;
        const int c = (idx & 7) * 4;
        float4 v = (r < TOK) ? ld4(g_q + base + r * HDIM + c)
                             : make_float4(0.f, 0.f, 0.f, 0.f);
        Qs[r * STQ + c + 0] = tfr(v.x);
        Qs[r * STQ + c + 1] = tfr(v.y);
        Qs[r * STQ + c + 2] = tfr(v.z);
        Qs[r * STQ + c + 3] = tfr(v.w);
    }
    for (int idx = tid; idx < 56 * 8; idx += 128) {
        const int r = idx >> 3;
        const int c = (idx & 7) * 4;
        float4 kv, vv;
        if (r < TOK) {
            kv = ld4(g_k + base + r * HDIM + c);
            vv = ld4(g_v + base + r * HDIM + c);
        } else {
            kv = make_float4(0.f, 0.f, 0.f, 0.f);
            vv = kv;
        }
        Ks[r * STQ + c + 0] = tfr(kv.x);
        Ks[r * STQ + c + 1] = tfr(kv.y);
        Ks[r * STQ + c + 2] = tfr(kv.z);
        Ks[r * STQ + c + 3] = tfr(kv.w);
        Vt[(c + 0) * STV + r] = tfr(vv.x);
        Vt[(c + 1) * STV + r] = tfr(vv.y);
        Vt[(c + 2) * STV + r] = tfr(vv.z);
        Vt[(c + 3) * STV + r] = tfr(vv.w);
    }
    __syncthreads();

    const int mrow = warp * 16;
    const uint32_t* Qu = reinterpret_cast<const uint32_t*>(Qs);
    const uint32_t* Ku = reinterpret_cast<const uint32_t*>(Ks);
    const uint32_t* Vu = reinterpret_cast<const uint32_t*>(Vt);

    float sacc[7][4];
#pragma unroll
    for (int j = 0; j < 7; j++)
#pragma unroll
        for (int e = 0; e < 4; e++) sacc[j][e] = 0.f;

#pragma unroll
    for (int kt = 0; kt < 4; kt++) {
        const int ko = kt * 8;
        uint32_t a0 = Qu[(mrow + g) * STQ + ko + tig];
        uint32_t a1 = Qu[(mrow + g + 8) * STQ + ko + tig];
        uint32_t a2 = Qu[(mrow + g) * STQ + ko + tig + 4];
        uint32_t a3 = Qu[(mrow + g + 8) * STQ + ko + tig + 4];
#pragma unroll
        for (int j = 0; j < 7; j++) {
            uint32_t b0 = Ku[(j * 8 + g) * STQ + ko + tig];
            uint32_t b1 = Ku[(j * 8 + g) * STQ + ko + tig + 4];
            mma_tf32(sacc[j], a0, a1, a2, a3, b0, b1);
        }
    }

    const int r1 = mrow + g;
    const int r2 = r1 + 8;
    const float* bmb = g_bm + (size_t)(((b & (NMASK - 1)) << 3) + h) * BMSTRIDE;
    const float* bm1 = bmb + (r1 < TOK ? r1 : 48) * BMROW;
    const float* bm2 = bmb + (r2 < TOK ? r2 : 48) * BMROW;

    float mx1 = -1e30f, mx2 = -1e30f;
#pragma unroll
    for (int j = 0; j < 7; j++) {
        const int cc = j * 8 + 2 * tig;
        const float2 bb1 = *reinterpret_cast<const float2*>(bm1 + cc);
        const float2 bb2 = *reinterpret_cast<const float2*>(bm2 + cc);
        sacc[j][0] = (cc     < TOK) ? sacc[j][0] + bb1.x : -1e30f;
        sacc[j][1] = (cc + 1 < TOK) ? sacc[j][1] + bb1.y : -1e30f;
        sacc[j][2] = (cc     < TOK) ? sacc[j][2] + bb2.x : -1e30f;
        sacc[j][3] = (cc + 1 < TOK) ? sacc[j][3] + bb2.y : -1e30f;
        mx1 = fmaxf(mx1, fmaxf(sacc[j][0], sacc[j][1]));
        mx2 = fmaxf(mx2, fmaxf(sacc[j][2], sacc[j][3]));
    }
    mx1 = fmaxf(mx1, __shfl_xor_sync(0xffffffffu, mx1, 1));
    mx1 = fmaxf(mx1, __shfl_xor_sync(0xffffffffu, mx1, 2));
    mx2 = fmaxf(mx2, __shfl_xor_sync(0xffffffffu, mx2, 1));
    mx2 = fmaxf(mx2, __shfl_xor_sync(0xffffffffu, mx2, 2));

    float s1 = 0.f, s2 = 0.f;
#pragma unroll
    for (int j = 0; j < 7; j++) {
        sacc[j][0] = __expf(sacc[j][0] - mx1);
        sacc[j][1] = __expf(sacc[j][1] - mx1);
        sacc[j][2] = __expf(sacc[j][2] - mx2);
        sacc[j][3] = __expf(sacc[j][3] - mx2);
        s1 += sacc[j][0] + sacc[j][1];
        s2 += sacc[j][2] + sacc[j][3];
    }
    s1 += __shfl_xor_sync(0xffffffffu, s1, 1);
    s1 += __shfl_xor_sync(0xffffffffu, s1, 2);
    s2 += __shfl_xor_sync(0xffffffffu, s2, 1);
    s2 += __shfl_xor_sync(0xffffffffu, s2, 2);
    const float inv1 = 1.f / s1;
    const float inv2 = 1.f / s2;

    __syncthreads();
#pragma unroll
    for (int j = 0; j < 7; j++) {
        const int cc = j * 8 + 2 * tig;
        st2(&Ps[r1 * STV + cc], make_float2(tfr(sacc[j][0] * inv1), tfr(sacc[j][1] * inv1)));
        st2(&Ps[r2 * STV + cc], make_float2(tfr(sacc[j][2] * inv2), tfr(sacc[j][3] * inv2)));
    }
    __syncwarp();

    const uint32_t* Pu = reinterpret_cast<const uint32_t*>(Ps);
    float oacc[4][4];
#pragma unroll
    for (int nt = 0; nt < 4; nt++)
#pragma unroll
        for (int e = 0; e < 4; e++) oacc[nt][e] = 0.f;

#pragma unroll
    for (int kt = 0; kt < 7; kt++) {
        const int ko = kt * 8;
        uint32_t a0 = Pu[(mrow + g) * STV + ko + tig];
        uint32_t a1 = Pu[(mrow + g + 8) * STV + ko + tig];
        uint32_t a2 = Pu[(mrow + g) * STV + ko + tig + 4];
        uint32_t a3 = Pu[(mrow + g + 8) * STV + ko + tig + 4];
#pragma unroll
        for (int nt = 0; nt < 4; nt++) {
            uint32_t b0 = Vu[(nt * 8 + g) * STV + ko + tig];
            uint32_t b1 = Vu[(nt * 8 + g) * STV + ko + tig + 4];
            mma_tf32(oacc[nt], a0, a1, a2, a3, b0, b1);
        }
    }

    // write O as fp16 (input to fp16 proj GEMM)
#pragma unroll
    for (int nt = 0; nt < 4; nt++) {
        const int d = nt * 8 + 2 * tig;
        if (r1 < TOK)
            *reinterpret_cast<__half2*>(
                &g_ath[(size_t)(b * TOK + r1) * KDIM + h * HDIM + d]) =
                __floats2half2_rn(oacc[nt][0], oacc[nt][1]);
        if (r2 < TOK)
            *reinterpret_cast<__half2*>(
                &g_ath[(size_t)(b * TOK + r2) * KDIM + h * HDIM + d]) =
                __floats2half2_rn(oacc[nt][2], oacc[nt][3]);
    }
}

// ---------------------------------------------------------------------------
extern "C" void kernel_launch(void* const* d_in, const int* in_sizes, int n_in,
                              void* d_out, int out_size)
{
    const float* x          = (const float*)d_in[0];
    const float* mask       = (const float*)d_in[1];
    const float* qkv_w      = (const float*)d_in[2];
    const float* qkv_b      = (const float*)d_in[3];
    const float* proj_w     = (const float*)d_in[4];
    const float* proj_b     = (const float*)d_in[5];
    const float* bias_table = (const float*)d_in[6];
    const int*   rel_index  = (const int*)d_in[7];
    float*       out        = (float*)d_out;

    __half *p_xh, *p_wqh, *p_wph, *p_ath;
    cudaGetSymbolAddress((void**)&p_xh,  g_xh);
    cudaGetSymbolAddress((void**)&p_wqh, g_wqh);
    cudaGetSymbolAddress((void**)&p_wph, g_wph);
    cudaGetSymbolAddress((void**)&p_ath, g_ath);

    const int smbytes = STG * STGW * 4;   // 4 * 5120 words * 4B = 81920 B
    cudaFuncSetAttribute(gemm_h<0>, cudaFuncAttributeMaxDynamicSharedMemorySize, smbytes);
    cudaFuncSetAttribute(gemm_h<1>, cudaFuncAttributeMaxDynamicSharedMemorySize, smbytes);

    // fp16 conversion (rn) of GEMM operands
    cvt2h<<<(MTOT * KDIM) / 8 / 256, 256>>>(x, p_xh);
    cvt2h<<<(768 * KDIM) / 8 / 256, 256>>>(qkv_w, p_wqh);
    cvt2h<<<(KDIM * KDIM) / 8 / 256, 256>>>(proj_w, p_wph);

    bm_precompute<<<NMASK * NH, 256>>>(bias_table, rel_index, mask);

    dim3 g1(768 / 128, MTOT / 128);
    gemm_h<0><<<g1, 256, smbytes>>>(p_xh, p_wqh, qkv_b, nullptr, 768);

    attn_mma<<<NWIN * NH, 128>>>();

    dim3 g2(KDIM / 128, MTOT / 128);
    gemm_h<1><<<g2, 256, smbytes>>>(p_ath, p_wph, proj_b, out, KDIM);
}

// round 14
// speedup vs baseline: 1.8016x; 1.1291x over previous
#include <cuda_runtime.h>
#include <cuda_fp16.h>
#include <cstdint>

#define TOK 49
#define HDIM 32
#define NH 8
#define NWIN 4096
#define MTOT (NWIN * TOK)   /* 200704 */
#define KDIM 256
#define NMASK 64
#define BMROW 50
#define BMSTRIDE 2452

// ---------------- scratch (device globals: allocation-free) ----------------
__device__ __half g_qh[NWIN * NH * TOK * HDIM];  // [b,h,t,d] fp16 (q pre-scaled)
__device__ __half g_kh[NWIN * NH * TOK * HDIM];
__device__ __half g_vh[NWIN * NH * TOK * HDIM];
__device__ __half g_ath[MTOT * KDIM];            // attention out, fp16
__device__ float  g_bm[NMASK * NH * BMSTRIDE];   // fused bias+mask per (w,h)
__device__ __half g_xh[MTOT * KDIM];             // x, fp16
__device__ __half g_wqh[768 * KDIM];             // qkv_w, fp16
__device__ __half g_wph[KDIM * KDIM];            // proj_w, fp16

__device__ __forceinline__ float4 ld4(const float* p) {
    return *reinterpret_cast<const float4*>(p);
}
__device__ __forceinline__ void st2(float* p, float2 v) {
    *reinterpret_cast<float2*>(p) = v;
}
__device__ __forceinline__ void cp16at(uint32_t smem_addr, const void* gmem_src) {
    asm volatile("cp.async.cg.shared.global [%0], [%1], 16;" :: "r"(smem_addr), "l"(gmem_src));
}

// fp16 tensor-core mma, fp32 accumulate
__device__ __forceinline__ void mma_f16(float c[4],
                                        uint32_t a0, uint32_t a1, uint32_t a2, uint32_t a3,
                                        uint32_t b0, uint32_t b1) {
    asm volatile(
        "mma.sync.aligned.m16n8k16.row.col.f32.f16.f16.f32 "
        "{%0,%1,%2,%3}, {%4,%5,%6,%7}, {%8,%9}, {%0,%1,%2,%3};"
        : "+f"(c[0]), "+f"(c[1]), "+f"(c[2]), "+f"(c[3])
        : "r"(a0), "r"(a1), "r"(a2), "r"(a3), "r"(b0), "r"(b1));
}

// ---------------------------------------------------------------------------
// fp32 -> fp16 conversion (8 elems/thread, 16B stores)
// ---------------------------------------------------------------------------
__global__ void cvt2h(const float* __restrict__ in, __half* __restrict__ out) {
    const size_t i = (size_t)(blockIdx.x * blockDim.x + threadIdx.x) * 8;
    float4 v0 = ld4(in + i), v1 = ld4(in + i + 4);
    __half2 h[4];
    h[0] = __floats2half2_rn(v0.x, v0.y);
    h[1] = __floats2half2_rn(v0.z, v0.w);
    h[2] = __floats2half2_rn(v1.x, v1.y);
    h[3] = __floats2half2_rn(v1.z, v1.w);
    *reinterpret_cast<uint4*>(out + i) = *reinterpret_cast<uint4*>(h);
}

// ---------------------------------------------------------------------------
// fp16 tensor-core GEMM (NT): proven structure (R12).
// MODE 0: scatter fp16 to g_qh/g_kh/g_vh (q scaled). MODE 1: fp32 C.
// ---------------------------------------------------------------------------
#define RS 20                  // smem row stride in 4B words (= 40 halves)
#define STG 4
#define AFW (128 * RS)
#define STGW (2 * AFW)

extern __shared__ uint32_t smw[];

template <int MODE>
__global__ __launch_bounds__(256, 2)
void gemm_h(const __half* __restrict__ A, const __half* __restrict__ B,
            const float* __restrict__ bias, float* __restrict__ C, int N)
{
    const int tid  = threadIdx.x;
    const int m0   = blockIdx.y * 128;
    const int n0   = blockIdx.x * 128;
    const int warp = tid >> 5;
    const int lane = tid & 31;
    const int g    = lane >> 2;
    const int tig  = lane & 3;
    const int wm   = warp & 1;
    const int wn   = warp >> 1;

    const int lr  = tid >> 1;
    const int lch = (tid & 1) * 16;
    const __half* Ag = A + (size_t)(m0 + lr) * KDIM + lch;
    const __half* Bg = B + (size_t)(n0 + lr) * KDIM + lch;
    uint32_t sbase;
    asm("{ .reg .u64 t; cvta.to.shared.u64 t, %1; cvt.u32.u64 %0, t; }"
        : "=r"(sbase) : "l"(smw));
    const uint32_t adst = sbase + (uint32_t)(lr * RS + (lch >> 1)) * 4;

    float acc[4][4][4];
#pragma unroll
    for (int mi = 0; mi < 4; mi++)
#pragma unroll
        for (int ni = 0; ni < 4; ni++)
#pragma unroll
            for (int e = 0; e < 4; e++) acc[mi][ni][e] = 0.f;

    auto issue = [&](int s, int kt) {
        const uint32_t so = (uint32_t)(s * STGW) * 4;
        cp16at(adst + so,      Ag + kt);
        cp16at(adst + so + 16, Ag + kt + 8);
        cp16at(adst + so + AFW * 4,      Bg + kt);
        cp16at(adst + so + AFW * 4 + 16, Bg + kt + 8);
        asm volatile("cp.async.commit_group;");
    };

    const int NT = KDIM / 32;
#pragma unroll
    for (int s = 0; s < STG - 1; s++) issue(s, s * 32);

#pragma unroll 1
    for (int iter = 0; iter < NT; iter++) {
        asm volatile("cp.async.wait_group %0;" :: "n"(STG - 2));
        __syncthreads();
        if (iter + STG - 1 < NT) issue((iter + STG - 1) % STG, (iter + STG - 1) * 32);
        else asm volatile("cp.async.commit_group;");

        const uint32_t* sA = smw + (iter % STG) * STGW;
        const uint32_t* sB = sA + AFW;
#pragma unroll
        for (int k8 = 0; k8 < 16; k8 += 8) {
            uint32_t a[4][4], bf[4][2];
#pragma unroll
            for (int mi = 0; mi < 4; mi++) {
                const int mg = (wm * 64 + mi * 16 + g) * RS;
                a[mi][0] = sA[mg + k8 + tig];
                a[mi][1] = sA[mg + 8 * RS + k8 + tig];
                a[mi][2] = sA[mg + k8 + tig + 4];
                a[mi][3] = sA[mg + 8 * RS + k8 + tig + 4];
            }
#pragma unroll
            for (int ni = 0; ni < 4; ni++) {
                const int ng = (wn * 32 + ni * 8 + g) * RS;
                bf[ni][0] = sB[ng + k8 + tig];
                bf[ni][1] = sB[ng + k8 + tig + 4];
            }
#pragma unroll
            for (int mi = 0; mi < 4; mi++)
#pragma unroll
                for (int ni = 0; ni < 4; ni++)
                    mma_f16(acc[mi][ni], a[mi][0], a[mi][1], a[mi][2], a[mi][3],
                            bf[ni][0], bf[ni][1]);
        }
    }

    if (MODE == 0) {
        const float SC = 0.17677669529663687f;
#pragma unroll
        for (int mi = 0; mi < 4; mi++) {
#pragma unroll
            for (int half = 0; half < 2; half++) {
                const int m  = m0 + wm * 64 + mi * 16 + g + half * 8;
                const int bw = m / TOK;
                const int t  = m - bw * TOK;
#pragma unroll
                for (int ni = 0; ni < 4; ni++) {
                    const int n     = n0 + wn * 32 + ni * 8 + 2 * tig;
                    const int which = n >> 8;
                    const int h     = (n >> 5) & 7;
                    const int d     = n & 31;
                    float vx = acc[mi][ni][half * 2 + 0] + bias[n + 0];
                    float vy = acc[mi][ni][half * 2 + 1] + bias[n + 1];
                    if (which == 0) { vx *= SC; vy *= SC; }
                    __half* dst = (which == 0) ? g_qh : (which == 1) ? g_kh : g_vh;
                    *reinterpret_cast<__half2*>(
                        &dst[(size_t)((bw * NH + h) * TOK + t) * HDIM + d]) =
                        __floats2half2_rn(vx, vy);
                }
            }
        }
    } else {
#pragma unroll
        for (int mi = 0; mi < 4; mi++) {
#pragma unroll
            for (int half = 0; half < 2; half++) {
                const int m = m0 + wm * 64 + mi * 16 + g + half * 8;
#pragma unroll
                for (int ni = 0; ni < 4; ni++) {
                    const int n = n0 + wn * 32 + ni * 8 + 2 * tig;
                    float2 v;
                    v.x = acc[mi][ni][half * 2 + 0] + bias[n + 0];
                    v.y = acc[mi][ni][half * 2 + 1] + bias[n + 1];
                    st2(C + (size_t)m * N + n, v);
                }
            }
        }
    }
}

// ---------------------------------------------------------------------------
// Precompute fused bias+mask (row stride 50)
// ---------------------------------------------------------------------------
__global__ void bm_precompute(const float* __restrict__ bias_table,
                              const int* __restrict__ rel_index,
                              const float* __restrict__ mask)
{
    const int w = blockIdx.x >> 3;
    float* dst = g_bm + (size_t)blockIdx.x * BMSTRIDE;
    const int h = blockIdx.x & 7;
    const float* mrow = mask + (size_t)w * (TOK * TOK);
    for (int e = threadIdx.x; e < TOK * TOK; e += 256) {
        const int i = e / TOK;
        const int j = e - i * TOK;
        dst[i * BMROW + j] = bias_table[rel_index[e] * NH + h] + mrow[e];
    }
}

// ---------------------------------------------------------------------------
// fp16 tensor-core attention: one block (4 warps) per (b,h).
// Smem (halves): Qh 64x40, Kh 56x40, Vt 32x72, Ps (aliases Qh/Kh) 64x72.
// S: 2 k16 steps x 7 col-tiles; PV: 4 k16 steps x 4 d-tiles.
// Padding: Q rows>=49, K rows>=49, Vt tokens 49..71, P cols 49..63 all zero.
// ---------------------------------------------------------------------------
#define QSW 20   // Q/K row stride in words
#define VSW 36   // Vt / Ps row stride in words

__global__ __launch_bounds__(128)
void attn_mma()
{
    __shared__ __half sh[7104];          // 14208 B
    __half* Qh = sh;                     // 64 * 40
    __half* Kh = sh + 2560;              // 56 * 40
    __half* Vt = sh + 4800;              // 32 * 72
    __half* Ps = sh;                     // 64 * 72 (alias, used after S phase)

    const int tid  = threadIdx.x;
    const int warp = tid >> 5;
    const int lane = tid & 31;
    const int g    = lane >> 2;
    const int tig  = lane & 3;
    const int bh   = blockIdx.x;
    const int b    = bh >> 3;
    const int h    = bh & 7;
    const size_t base = (size_t)bh * (TOK * HDIM);

    const uint4 z4 = make_uint4(0, 0, 0, 0);

    // ---- stage Q: 64 rows x 32 halves = 4 uint4 chunks per row ----
    for (int idx = tid; idx < 64 * 4; idx += 128) {
        const int r = idx >> 2, part = idx & 3;
        uint4 v = (r < TOK)
            ? *reinterpret_cast<const uint4*>(g_qh + base + r * HDIM + part * 8) : z4;
        *reinterpret_cast<uint4*>(Qh + r * 40 + part * 8) = v;
    }
    // ---- stage K: 56 rows x 4 chunks (rows >=49 zero) ----
    for (int idx = tid; idx < 56 * 4; idx += 128) {
        const int r = idx >> 2, part = idx & 3;
        uint4 v = (r < TOK)
            ? *reinterpret_cast<const uint4*>(g_kh + base + r * HDIM + part * 8) : z4;
        *reinterpret_cast<uint4*>(Kh + r * 40 + part * 8) = v;
    }
    // ---- zero Vt padding tokens 49..71 ONLY (token 48 is valid data) ----
    for (int idx = tid; idx < 32 * 12; idx += 128) {
        const int d = idx / 12, w = idx % 12;
        if (w == 0) Vt[d * 72 + 49] = __ushort_as_half((unsigned short)0);
        else reinterpret_cast<uint32_t*>(Vt)[d * VSW + 24 + w] = 0;   // halves 50..71
    }
    // ---- stage V transposed: Vt[d][token] for tokens 0..48 ----
    for (int idx = tid; idx < TOK * 4; idx += 128) {
        const int r = idx >> 2;            // token
        const int c = (idx & 3) * 8;       // d base
        uint4 v = *reinterpret_cast<const uint4*>(g_vh + base + r * HDIM + c);
        const __half* hp = reinterpret_cast<const __half*>(&v);
#pragma unroll
        for (int i = 0; i < 8; i++)
            Vt[(c + i) * 72 + r] = hp[i];
    }
    __syncthreads();

    const int mrow = warp * 16;
    const uint32_t* Qw = reinterpret_cast<const uint32_t*>(Qh);
    const uint32_t* Kw = reinterpret_cast<const uint32_t*>(Kh);
    const uint32_t* Vw = reinterpret_cast<const uint32_t*>(Vt);

    // ---- S = Q K^T : 2 k16 steps, 7 col-tiles ----
    float sacc[7][4];
#pragma unroll
    for (int j = 0; j < 7; j++)
#pragma unroll
        for (int e = 0; e < 4; e++) sacc[j][e] = 0.f;

#pragma unroll
    for (int st = 0; st < 2; st++) {
        const int ko = st * 8;
        uint32_t a0 = Qw[(mrow + g) * QSW + ko + tig];
        uint32_t a1 = Qw[(mrow + g + 8) * QSW + ko + tig];
        uint32_t a2 = Qw[(mrow + g) * QSW + ko + tig + 4];
        uint32_t a3 = Qw[(mrow + g + 8) * QSW + ko + tig + 4];
#pragma unroll
        for (int j = 0; j < 7; j++) {
            uint32_t b0 = Kw[(j * 8 + g) * QSW + ko + tig];
            uint32_t b1 = Kw[(j * 8 + g) * QSW + ko + tig + 4];
            mma_f16(sacc[j], a0, a1, a2, a3, b0, b1);
        }
    }

    // ---- bias+mask + softmax (fp32) ----
    const int r1 = mrow + g;
    const int r2 = r1 + 8;
    const float* bmb = g_bm + (size_t)(((b & (NMASK - 1)) << 3) + h) * BMSTRIDE;
    const float* bm1 = bmb + (r1 < TOK ? r1 : 48) * BMROW;
    const float* bm2 = bmb + (r2 < TOK ? r2 : 48) * BMROW;

    float mx1 = -1e30f, mx2 = -1e30f;
#pragma unroll
    for (int j = 0; j < 7; j++) {
        const int cc = j * 8 + 2 * tig;
        const float2 bb1 = *reinterpret_cast<const float2*>(bm1 + cc);
        const float2 bb2 = *reinterpret_cast<const float2*>(bm2 + cc);
        sacc[j][0] = (cc     < TOK) ? sacc[j][0] + bb1.x : -1e30f;
        sacc[j][1] = (cc + 1 < TOK) ? sacc[j][1] + bb1.y : -1e30f;
        sacc[j][2] = (cc     < TOK) ? sacc[j][2] + bb2.x : -1e30f;
        sacc[j][3] = (cc + 1 < TOK) ? sacc[j][3] + bb2.y : -1e30f;
        mx1 = fmaxf(mx1, fmaxf(sacc[j][0], sacc[j][1]));
        mx2 = fmaxf(mx2, fmaxf(sacc[j][2], sacc[j][3]));
    }
    mx1 = fmaxf(mx1, __shfl_xor_sync(0xffffffffu, mx1, 1));
    mx1 = fmaxf(mx1, __shfl_xor_sync(0xffffffffu, mx1, 2));
    mx2 = fmaxf(mx2, __shfl_xor_sync(0xffffffffu, mx2, 1));
    mx2 = fmaxf(mx2, __shfl_xor_sync(0xffffffffu, mx2, 2));

    float s1 = 0.f, s2 = 0.f;
#pragma unroll
    for (int j = 0; j < 7; j++) {
        sacc[j][0] = __expf(sacc[j][0] - mx1);
        sacc[j][1] = __expf(sacc[j][1] - mx1);
        sacc[j][2] = __expf(sacc[j][2] - mx2);
        sacc[j][3] = __expf(sacc[j][3] - mx2);
        s1 += sacc[j][0] + sacc[j][1];
        s2 += sacc[j][2] + sacc[j][3];
    }
    s1 += __shfl_xor_sync(0xffffffffu, s1, 1);
    s1 += __shfl_xor_sync(0xffffffffu, s1, 2);
    s2 += __shfl_xor_sync(0xffffffffu, s2, 1);
    s2 += __shfl_xor_sync(0xffffffffu, s2, 2);
    const float inv1 = 1.f / s1;
    const float inv2 = 1.f / s2;

    // ---- P -> smem fp16 (aliases Qh/Kh; wait for all S reads first) ----
    __syncthreads();
#pragma unroll
    for (int j = 0; j < 7; j++) {
        const int cc = j * 8 + 2 * tig;
        *reinterpret_cast<__half2*>(Ps + r1 * 72 + cc) =
            __floats2half2_rn(sacc[j][0] * inv1, sacc[j][1] * inv1);
        *reinterpret_cast<__half2*>(Ps + r2 * 72 + cc) =
            __floats2half2_rn(sacc[j][2] * inv2, sacc[j][3] * inv2);
    }
    // zero P tokens 56..63 of own rows
    {
        __half2 z = __floats2half2_rn(0.f, 0.f);
        *reinterpret_cast<__half2*>(Ps + r1 * 72 + 56 + 2 * tig) = z;
        *reinterpret_cast<__half2*>(Ps + r2 * 72 + 56 + 2 * tig) = z;
    }
    __syncwarp();

    // ---- O = P @ V : 4 k16 steps, 4 d-tiles ----
    const uint32_t* Pw = reinterpret_cast<const uint32_t*>(Ps);
    float oacc[4][4];
#pragma unroll
    for (int nt = 0; nt < 4; nt++)
#pragma unroll
        for (int e = 0; e < 4; e++) oacc[nt][e] = 0.f;

#pragma unroll
    for (int st = 0; st < 4; st++) {
        const int ko = st * 8;
        uint32_t a0 = Pw[(mrow + g) * VSW + ko + tig];
        uint32_t a1 = Pw[(mrow + g + 8) * VSW + ko + tig];
        uint32_t a2 = Pw[(mrow + g) * VSW + ko + tig + 4];
        uint32_t a3 = Pw[(mrow + g + 8) * VSW + ko + tig + 4];
#pragma unroll
        for (int nt = 0; nt < 4; nt++) {
            uint32_t b0 = Vw[(nt * 8 + g) * VSW + ko + tig];
            uint32_t b1 = Vw[(nt * 8 + g) * VSW + ko + tig + 4];
            mma_f16(oacc[nt], a0, a1, a2, a3, b0, b1);
        }
    }

    // ---- write O fp16 ----
#pragma unroll
    for (int nt = 0; nt < 4; nt++) {
        const int d = nt * 8 + 2 * tig;
        if (r1 < TOK)
            *reinterpret_cast<__half2*>(
                &g_ath[(size_t)(b * TOK + r1) * KDIM + h * HDIM + d]) =
                __floats2half2_rn(oacc[nt][0], oacc[nt][1]);
        if (r2 < TOK)
            *reinterpret_cast<__half2*>(
                &g_ath[(size_t)(b * TOK + r2) * KDIM + h * HDIM + d]) =
                __floats2half2_rn(oacc[nt][2], oacc[nt][3]);
    }
}

// ---------------------------------------------------------------------------
extern "C" void kernel_launch(void* const* d_in, const int* in_sizes, int n_in,
                              void* d_out, int out_size)
{
    const float* x          = (const float*)d_in[0];
    const float* mask       = (const float*)d_in[1];
    const float* qkv_w      = (const float*)d_in[2];
    const float* qkv_b      = (const float*)d_in[3];
    const float* proj_w     = (const float*)d_in[4];
    const float* proj_b     = (const float*)d_in[5];
    const float* bias_table = (const float*)d_in[6];
    const int*   rel_index  = (const int*)d_in[7];
    float*       out        = (float*)d_out;

    __half *p_xh, *p_wqh, *p_wph, *p_ath;
    cudaGetSymbolAddress((void**)&p_xh,  g_xh);
    cudaGetSymbolAddress((void**)&p_wqh, g_wqh);
    cudaGetSymbolAddress((void**)&p_wph, g_wph);
    cudaGetSymbolAddress((void**)&p_ath, g_ath);

    const int smbytes = STG * STGW * 4;   // 81920 B
    cudaFuncSetAttribute(gemm_h<0>, cudaFuncAttributeMaxDynamicSharedMemorySize, smbytes);
    cudaFuncSetAttribute(gemm_h<1>, cudaFuncAttributeMaxDynamicSharedMemorySize, smbytes);

    cvt2h<<<(MTOT * KDIM) / 8 / 256, 256>>>(x, p_xh);
    cvt2h<<<(768 * KDIM) / 8 / 256, 256>>>(qkv_w, p_wqh);
    cvt2h<<<(KDIM * KDIM) / 8 / 256, 256>>>(proj_w, p_wph);

    bm_precompute<<<NMASK * NH, 256>>>(bias_table, rel_index, mask);

    dim3 g1(768 / 128, MTOT / 128);
    gemm_h<0><<<g1, 256, smbytes>>>(p_xh, p_wqh, qkv_b, nullptr, 768);

    attn_mma<<<NWIN * NH, 128>>>();

    dim3 g2(KDIM / 128, MTOT / 128);
    gemm_h<1><<<g2, 256, smbytes>>>(p_ath, p_wph, proj_b, out, KDIM);
}

// round 15
// speedup vs baseline: 1.8758x; 1.0412x over previous
#include <cuda_runtime.h>
#include <cuda_fp16.h>
#include <cstdint>

#define TOK 49
#define HDIM 32
#define NH 8
#define NWIN 4096
#define MTOT (NWIN * TOK)   /* 200704 */
#define KDIM 256
#define NMASK 64
#define BMROW 50
#define BMSTRIDE 2452

// ---------------- scratch (device globals: allocation-free) ----------------
__device__ __half g_qh[NWIN * NH * TOK * HDIM];  // [b,h,t,d] fp16 (q pre-scaled)
__device__ __half g_kh[NWIN * NH * TOK * HDIM];
__device__ __half g_vh[NWIN * NH * TOK * HDIM];
__device__ __half g_ath[MTOT * KDIM];            // attention out, fp16
__device__ float  g_bm[NMASK * NH * BMSTRIDE];   // fused bias+mask per (w,h)
__device__ __half g_xh[MTOT * KDIM];             // x, fp16
__device__ __half g_wqh[768 * KDIM];             // qkv_w, fp16
__device__ __half g_wph[KDIM * KDIM];            // proj_w, fp16

__device__ __forceinline__ float4 ld4(const float* p) {
    return *reinterpret_cast<const float4*>(p);
}
__device__ __forceinline__ void st2(float* p, float2 v) {
    *reinterpret_cast<float2*>(p) = v;
}
__device__ __forceinline__ void cp16at(uint32_t smem_addr, const void* gmem_src) {
    asm volatile("cp.async.cg.shared.global [%0], [%1], 16;" :: "r"(smem_addr), "l"(gmem_src));
}
__device__ __forceinline__ void ldsm4(uint32_t r[4], uint32_t addr) {
    asm volatile("ldmatrix.sync.aligned.m8n8.x4.shared.b16 {%0,%1,%2,%3}, [%4];"
                 : "=r"(r[0]), "=r"(r[1]), "=r"(r[2]), "=r"(r[3]) : "r"(addr));
}

// fp16 tensor-core mma, fp32 accumulate
__device__ __forceinline__ void mma_f16(float c[4],
                                        uint32_t a0, uint32_t a1, uint32_t a2, uint32_t a3,
                                        uint32_t b0, uint32_t b1) {
    asm volatile(
        "mma.sync.aligned.m16n8k16.row.col.f32.f16.f16.f32 "
        "{%0,%1,%2,%3}, {%4,%5,%6,%7}, {%8,%9}, {%0,%1,%2,%3};"
        : "+f"(c[0]), "+f"(c[1]), "+f"(c[2]), "+f"(c[3])
        : "r"(a0), "r"(a1), "r"(a2), "r"(a3), "r"(b0), "r"(b1));
}

// ---------------------------------------------------------------------------
// fp32 -> fp16 conversion (8 elems/thread, 16B stores)
// ---------------------------------------------------------------------------
__global__ void cvt2h(const float* __restrict__ in, __half* __restrict__ out) {
    const size_t i = (size_t)(blockIdx.x * blockDim.x + threadIdx.x) * 8;
    float4 v0 = ld4(in + i), v1 = ld4(in + i + 4);
    __half2 h[4];
    h[0] = __floats2half2_rn(v0.x, v0.y);
    h[1] = __floats2half2_rn(v0.z, v0.w);
    h[2] = __floats2half2_rn(v1.x, v1.y);
    h[3] = __floats2half2_rn(v1.z, v1.w);
    *reinterpret_cast<uint4*>(out + i) = *reinterpret_cast<uint4*>(h);
}

// ---------------------------------------------------------------------------
// fp16 tensor-core GEMM (NT) with ldmatrix fragment loads.
// Block 128x128, BK=32 halves, 8 warps (2m x 4n), warp tile 64x32,
// 4-stage cp.async pipeline. Per k16 step: 4 ldmatrix.x4 (A) + 2 (B).
// MODE 0: scatter fp16 to g_qh/g_kh/g_vh (q scaled). MODE 1: fp32 C.
// ---------------------------------------------------------------------------
#define RS 20                  // smem row stride in 4B words (= 40 halves, 80 B)
#define STG 4
#define AFW (128 * RS)
#define STGW (2 * AFW)

extern __shared__ uint32_t smw[];

template <int MODE>
__global__ __launch_bounds__(256, 2)
void gemm_h(const __half* __restrict__ A, const __half* __restrict__ B,
            const float* __restrict__ bias, float* __restrict__ C, int N)
{
    const int tid  = threadIdx.x;
    const int m0   = blockIdx.y * 128;
    const int n0   = blockIdx.x * 128;
    const int warp = tid >> 5;
    const int lane = tid & 31;
    const int g    = lane >> 2;
    const int tig  = lane & 3;
    const int wm   = warp & 1;
    const int wn   = warp >> 1;

    const int lr  = tid >> 1;
    const int lch = (tid & 1) * 16;
    const __half* Ag = A + (size_t)(m0 + lr) * KDIM + lch;
    const __half* Bg = B + (size_t)(n0 + lr) * KDIM + lch;
    uint32_t sbase;
    asm("{ .reg .u64 t; cvta.to.shared.u64 t, %1; cvt.u32.u64 %0, t; }"
        : "=r"(sbase) : "l"(smw));
    const uint32_t adst = sbase + (uint32_t)(lr * RS + (lch >> 1)) * 4;

    // ldmatrix per-lane byte offsets within a stage
    // A: row = wm*64 + (lane&15) (+ mi*16), k-half = (lane>>4)*8 (+ ks*16)
    const uint32_t aoffB = (uint32_t)((wm * 64 + (lane & 15)) * 80 + (lane >> 4) * 16);
    // B: row = wn*32 + (lane&7) + ((lane>>4)<<3) (+ ni2*16), k-half = ((lane>>3)&1)*8
    const uint32_t boffB = (uint32_t)(AFW * 4
                         + (wn * 32 + (lane & 7) + ((lane >> 4) << 3)) * 80
                         + ((lane >> 3) & 1) * 16);

    float acc[4][4][4];
#pragma unroll
    for (int mi = 0; mi < 4; mi++)
#pragma unroll
        for (int ni = 0; ni < 4; ni++)
#pragma unroll
            for (int e = 0; e < 4; e++) acc[mi][ni][e] = 0.f;

    auto issue = [&](int s, int kt) {
        const uint32_t so = (uint32_t)(s * STGW) * 4;
        cp16at(adst + so,      Ag + kt);
        cp16at(adst + so + 16, Ag + kt + 8);
        cp16at(adst + so + AFW * 4,      Bg + kt);
        cp16at(adst + so + AFW * 4 + 16, Bg + kt + 8);
        asm volatile("cp.async.commit_group;");
    };

    const int NT = KDIM / 32;
#pragma unroll
    for (int s = 0; s < STG - 1; s++) issue(s, s * 32);

#pragma unroll 1
    for (int iter = 0; iter < NT; iter++) {
        asm volatile("cp.async.wait_group %0;" :: "n"(STG - 2));
        __syncthreads();
        if (iter + STG - 1 < NT) issue((iter + STG - 1) % STG, (iter + STG - 1) * 32);
        else asm volatile("cp.async.commit_group;");

        const uint32_t stB = sbase + (uint32_t)((iter % STG) * STGW) * 4;
#pragma unroll
        for (int ks = 0; ks < 2; ks++) {          // two k16 steps (+32B each)
            uint32_t a[4][4], bf[8];
#pragma unroll
            for (int mi = 0; mi < 4; mi++)
                ldsm4(a[mi], stB + aoffB + mi * 1280 + ks * 32);
            ldsm4(&bf[0], stB + boffB + ks * 32);          // ni 0,1
            ldsm4(&bf[4], stB + boffB + 1280 + ks * 32);   // ni 2,3
#pragma unroll
            for (int mi = 0; mi < 4; mi++)
#pragma unroll
                for (int ni = 0; ni < 4; ni++)
                    mma_f16(acc[mi][ni], a[mi][0], a[mi][1], a[mi][2], a[mi][3],
                            bf[ni * 2], bf[ni * 2 + 1]);
        }
    }

    if (MODE == 0) {
        const float SC = 0.17677669529663687f;
#pragma unroll
        for (int mi = 0; mi < 4; mi++) {
#pragma unroll
            for (int half = 0; half < 2; half++) {
                const int m  = m0 + wm * 64 + mi * 16 + g + half * 8;
                const int bw = m / TOK;
                const int t  = m - bw * TOK;
#pragma unroll
                for (int ni = 0; ni < 4; ni++) {
                    const int n     = n0 + wn * 32 + ni * 8 + 2 * tig;
                    const int which = n >> 8;
                    const int h     = (n >> 5) & 7;
                    const int d     = n & 31;
                    float vx = acc[mi][ni][half * 2 + 0] + bias[n + 0];
                    float vy = acc[mi][ni][half * 2 + 1] + bias[n + 1];
                    if (which == 0) { vx *= SC; vy *= SC; }
                    __half* dst = (which == 0) ? g_qh : (which == 1) ? g_kh : g_vh;
                    *reinterpret_cast<__half2*>(
                        &dst[(size_t)((bw * NH + h) * TOK + t) * HDIM + d]) =
                        __floats2half2_rn(vx, vy);
                }
            }
        }
    } else {
#pragma unroll
        for (int mi = 0; mi < 4; mi++) {
#pragma unroll
            for (int half = 0; half < 2; half++) {
                const int m = m0 + wm * 64 + mi * 16 + g + half * 8;
#pragma unroll
                for (int ni = 0; ni < 4; ni++) {
                    const int n = n0 + wn * 32 + ni * 8 + 2 * tig;
                    float2 v;
                    v.x = acc[mi][ni][half * 2 + 0] + bias[n + 0];
                    v.y = acc[mi][ni][half * 2 + 1] + bias[n + 1];
                    st2(C + (size_t)m * N + n, v);
                }
            }
        }
    }
}

// ---------------------------------------------------------------------------
// Precompute fused bias+mask (row stride 50)
// ---------------------------------------------------------------------------
__global__ void bm_precompute(const float* __restrict__ bias_table,
                              const int* __restrict__ rel_index,
                              const float* __restrict__ mask)
{
    const int w = blockIdx.x >> 3;
    float* dst = g_bm + (size_t)blockIdx.x * BMSTRIDE;
    const int h = blockIdx.x & 7;
    const float* mrow = mask + (size_t)w * (TOK * TOK);
    for (int e = threadIdx.x; e < TOK * TOK; e += 256) {
        const int i = e / TOK;
        const int j = e - i * TOK;
        dst[i * BMROW + j] = bias_table[rel_index[e] * NH + h] + mrow[e];
    }
}

// ---------------------------------------------------------------------------
// fp16 tensor-core attention (unchanged from R14 — known good)
// ---------------------------------------------------------------------------
#define QSW 20   // Q/K row stride in words
#define VSW 36   // Vt / Ps row stride in words

__global__ __launch_bounds__(128)
void attn_mma()
{
    __shared__ __half sh[7104];
    __half* Qh = sh;                     // 64 * 40
    __half* Kh = sh + 2560;              // 56 * 40
    __half* Vt = sh + 4800;              // 32 * 72
    __half* Ps = sh;                     // 64 * 72 (alias)

    const int tid  = threadIdx.x;
    const int warp = tid >> 5;
    const int lane = tid & 31;
    const int g    = lane >> 2;
    const int tig  = lane & 3;
    const int bh   = blockIdx.x;
    const int b    = bh >> 3;
    const int h    = bh & 7;
    const size_t base = (size_t)bh * (TOK * HDIM);

    const uint4 z4 = make_uint4(0, 0, 0, 0);

    for (int idx = tid; idx < 64 * 4; idx += 128) {
        const int r = idx >> 2, part = idx & 3;
        uint4 v = (r < TOK)
            ? *reinterpret_cast<const uint4*>(g_qh + base + r * HDIM + part * 8) : z4;
        *reinterpret_cast<uint4*>(Qh + r * 40 + part * 8) = v;
    }
    for (int idx = tid; idx < 56 * 4; idx += 128) {
        const int r = idx >> 2, part = idx & 3;
        uint4 v = (r < TOK)
            ? *reinterpret_cast<const uint4*>(g_kh + base + r * HDIM + part * 8) : z4;
        *reinterpret_cast<uint4*>(Kh + r * 40 + part * 8) = v;
    }
    for (int idx = tid; idx < 32 * 12; idx += 128) {
        const int d = idx / 12, w = idx % 12;
        if (w == 0) Vt[d * 72 + 49] = __ushort_as_half((unsigned short)0);
        else reinterpret_cast<uint32_t*>(Vt)[d * VSW + 24 + w] = 0;
    }
    for (int idx = tid; idx < TOK * 4; idx += 128) {
        const int r = idx >> 2;
        const int c = (idx & 3) * 8;
        uint4 v = *reinterpret_cast<const uint4*>(g_vh + base + r * HDIM + c);
        const __half* hp = reinterpret_cast<const __half*>(&v);
#pragma unroll
        for (int i = 0; i < 8; i++)
            Vt[(c + i) * 72 + r] = hp[i];
    }
    __syncthreads();

    const int mrow = warp * 16;
    const uint32_t* Qw = reinterpret_cast<const uint32_t*>(Qh);
    const uint32_t* Kw = reinterpret_cast<const uint32_t*>(Kh);
    const uint32_t* Vw = reinterpret_cast<const uint32_t*>(Vt);

    float sacc[7][4];
#pragma unroll
    for (int j = 0; j < 7; j++)
#pragma unroll
        for (int e = 0; e < 4; e++) sacc[j][e] = 0.f;

#pragma unroll
    for (int st = 0; st < 2; st++) {
        const int ko = st * 8;
        uint32_t a0 = Qw[(mrow + g) * QSW + ko + tig];
        uint32_t a1 = Qw[(mrow + g + 8) * QSW + ko + tig];
        uint32_t a2 = Qw[(mrow + g) * QSW + ko + tig + 4];
        uint32_t a3 = Qw[(mrow + g + 8) * QSW + ko + tig + 4];
#pragma unroll
        for (int j = 0; j < 7; j++) {
            uint32_t b0 = Kw[(j * 8 + g) * QSW + ko + tig];
            uint32_t b1 = Kw[(j * 8 + g) * QSW + ko + tig + 4];
            mma_f16(sacc[j], a0, a1, a2, a3, b0, b1);
        }
    }

    const int r1 = mrow + g;
    const int r2 = r1 + 8;
    const float* bmb = g_bm + (size_t)(((b & (NMASK - 1)) << 3) + h) * BMSTRIDE;
    const float* bm1 = bmb + (r1 < TOK ? r1 : 48) * BMROW;
    const float* bm2 = bmb + (r2 < TOK ? r2 : 48) * BMROW;

    float mx1 = -1e30f, mx2 = -1e30f;
#pragma unroll
    for (int j = 0; j < 7; j++) {
        const int cc = j * 8 + 2 * tig;
        const float2 bb1 = *reinterpret_cast<const float2*>(bm1 + cc);
        const float2 bb2 = *reinterpret_cast<const float2*>(bm2 + cc);
        sacc[j][0] = (cc     < TOK) ? sacc[j][0] + bb1.x : -1e30f;
        sacc[j][1] = (cc + 1 < TOK) ? sacc[j][1] + bb1.y : -1e30f;
        sacc[j][2] = (cc     < TOK) ? sacc[j][2] + bb2.x : -1e30f;
        sacc[j][3] = (cc + 1 < TOK) ? sacc[j][3] + bb2.y : -1e30f;
        mx1 = fmaxf(mx1, fmaxf(sacc[j][0], sacc[j][1]));
        mx2 = fmaxf(mx2, fmaxf(sacc[j][2], sacc[j][3]));
    }
    mx1 = fmaxf(mx1, __shfl_xor_sync(0xffffffffu, mx1, 1));
    mx1 = fmaxf(mx1, __shfl_xor_sync(0xffffffffu, mx1, 2));
    mx2 = fmaxf(mx2, __shfl_xor_sync(0xffffffffu, mx2, 1));
    mx2 = fmaxf(mx2, __shfl_xor_sync(0xffffffffu, mx2, 2));

    float s1 = 0.f, s2 = 0.f;
#pragma unroll
    for (int j = 0; j < 7; j++) {
        sacc[j][0] = __expf(sacc[j][0] - mx1);
        sacc[j][1] = __expf(sacc[j][1] - mx1);
        sacc[j][2] = __expf(sacc[j][2] - mx2);
        sacc[j][3] = __expf(sacc[j][3] - mx2);
        s1 += sacc[j][0] + sacc[j][1];
        s2 += sacc[j][2] + sacc[j][3];
    }
    s1 += __shfl_xor_sync(0xffffffffu, s1, 1);
    s1 += __shfl_xor_sync(0xffffffffu, s1, 2);
    s2 += __shfl_xor_sync(0xffffffffu, s2, 1);
    s2 += __shfl_xor_sync(0xffffffffu, s2, 2);
    const float inv1 = 1.f / s1;
    const float inv2 = 1.f / s2;

    __syncthreads();
#pragma unroll
    for (int j = 0; j < 7; j++) {
        const int cc = j * 8 + 2 * tig;
        *reinterpret_cast<__half2*>(Ps + r1 * 72 + cc) =
            __floats2half2_rn(sacc[j][0] * inv1, sacc[j][1] * inv1);
        *reinterpret_cast<__half2*>(Ps + r2 * 72 + cc) =
            __floats2half2_rn(sacc[j][2] * inv2, sacc[j][3] * inv2);
    }
    {
        __half2 z = __floats2half2_rn(0.f, 0.f);
        *reinterpret_cast<__half2*>(Ps + r1 * 72 + 56 + 2 * tig) = z;
        *reinterpret_cast<__half2*>(Ps + r2 * 72 + 56 + 2 * tig) = z;
    }
    __syncwarp();

    const uint32_t* Pw = reinterpret_cast<const uint32_t*>(Ps);
    float oacc[4][4];
#pragma unroll
    for (int nt = 0; nt < 4; nt++)
#pragma unroll
        for (int e = 0; e < 4; e++) oacc[nt][e] = 0.f;

#pragma unroll
    for (int st = 0; st < 4; st++) {
        const int ko = st * 8;
        uint32_t a0 = Pw[(mrow + g) * VSW + ko + tig];
        uint32_t a1 = Pw[(mrow + g + 8) * VSW + ko + tig];
        uint32_t a2 = Pw[(mrow + g) * VSW + ko + tig + 4];
        uint32_t a3 = Pw[(mrow + g + 8) * VSW + ko + tig + 4];
#pragma unroll
        for (int nt = 0; nt < 4; nt++) {
            uint32_t b0 = Vw[(nt * 8 + g) * VSW + ko + tig];
            uint32_t b1 = Vw[(nt * 8 + g) * VSW + ko + tig + 4];
            mma_f16(oacc[nt], a0, a1, a2, a3, b0, b1);
        }
    }

#pragma unroll
    for (int nt = 0; nt < 4; nt++) {
        const int d = nt * 8 + 2 * tig;
        if (r1 < TOK)
            *reinterpret_cast<__half2*>(
                &g_ath[(size_t)(b * TOK + r1) * KDIM + h * HDIM + d]) =
                __floats2half2_rn(oacc[nt][0], oacc[nt][1]);
        if (r2 < TOK)
            *reinterpret_cast<__half2*>(
                &g_ath[(size_t)(b * TOK + r2) * KDIM + h * HDIM + d]) =
                __floats2half2_rn(oacc[nt][2], oacc[nt][3]);
    }
}

// ---------------------------------------------------------------------------
extern "C" void kernel_launch(void* const* d_in, const int* in_sizes, int n_in,
                              void* d_out, int out_size)
{
    const float* x          = (const float*)d_in[0];
    const float* mask       = (const float*)d_in[1];
    const float* qkv_w      = (const float*)d_in[2];
    const float* qkv_b      = (const float*)d_in[3];
    const float* proj_w     = (const float*)d_in[4];
    const float* proj_b     = (const float*)d_in[5];
    const float* bias_table = (const float*)d_in[6];
    const int*   rel_index  = (const int*)d_in[7];
    float*       out        = (float*)d_out;

    __half *p_xh, *p_wqh, *p_wph, *p_ath;
    cudaGetSymbolAddress((void**)&p_xh,  g_xh);
    cudaGetSymbolAddress((void**)&p_wqh, g_wqh);
    cudaGetSymbolAddress((void**)&p_wph, g_wph);
    cudaGetSymbolAddress((void**)&p_ath, g_ath);

    const int smbytes = STG * STGW * 4;   // 81920 B
    cudaFuncSetAttribute(gemm_h<0>, cudaFuncAttributeMaxDynamicSharedMemorySize, smbytes);
    cudaFuncSetAttribute(gemm_h<1>, cudaFuncAttributeMaxDynamicSharedMemorySize, smbytes);

    cvt2h<<<(MTOT * KDIM) / 8 / 256, 256>>>(x, p_xh);
    cvt2h<<<(768 * KDIM) / 8 / 256, 256>>>(qkv_w, p_wqh);
    cvt2h<<<(KDIM * KDIM) / 8 / 256, 256>>>(proj_w, p_wph);

    bm_precompute<<<NMASK * NH, 256>>>(bias_table, rel_index, mask);

    dim3 g1(768 / 128, MTOT / 128);
    gemm_h<0><<<g1, 256, smbytes>>>(p_xh, p_wqh, qkv_b, nullptr, 768);

    attn_mma<<<NWIN * NH, 128>>>();

    dim3 g2(KDIM / 128, MTOT / 128);
    gemm_h<1><<<g2, 256, smbytes>>>(p_ath, p_wph, proj_b, out, KDIM);
}